// round 1
// baseline (speedup 1.0000x reference)
#include <cuda_runtime.h>
#include <math.h>

#define NN 4096
#define DD 256
#define SS 32
#define KK 4
#define NDOUT (NN*DD)
#define NNZ_MAX (1<<20)
#define FULLM 0xffffffffu
#define MZC 224
#define SCMAX 512

// ---------------- scratch (device globals; no allocation allowed) -----------
__device__ int   g_rowptr[NN+1];
__device__ int   g_cols[NNZ_MAX];
__device__ float g_lvals[NNZ_MAX];
__device__ __align__(16) float g_Z  [KK*NN*SS];
__device__ __align__(16) float g_MZ [KK*NN*SS];
__device__ __align__(16) float g_V  [KK*NN*SS];
__device__ float g_M   [KK*SS*SS];
__device__ float g_Mp  [KK*16*SS*SS];
__device__ float g_Minv[KK*SS*SS];
__device__ float g_Hagg[NN*DD];
__device__ float g_w[KK];

// ---------------- init: w = softmax(hop_weights), zero scalar outputs -------
__global__ void k_init(const float* hw, float* out, int out_size) {
    if (threadIdx.x == 0) {
        float m = hw[0];
        for (int i = 1; i < KK; i++) m = fmaxf(m, hw[i]);
        float e[KK]; float s = 0.f;
        for (int i = 0; i < KK; i++) { e[i] = expf(hw[i] - m); s += e[i]; }
        for (int i = 0; i < KK; i++) {
            float w = e[i] / s;
            g_w[i] = w;
            if (NDOUT + 2 + i < out_size) out[NDOUT + 2 + i] = w;
        }
        if (NDOUT     < out_size) out[NDOUT]     = 0.f;
        if (NDOUT + 1 < out_size) out[NDOUT + 1] = 0.f;
        g_rowptr[0] = 0;
    }
}

// ---------------- CSR build: count ------------------------------------------
__global__ void k_count(const float* __restrict__ A) {
    int row  = blockIdx.x * 8 + (threadIdx.x >> 5);
    int lane = threadIdx.x & 31;
    if (row >= NN) return;
    const float* ar = A + (size_t)row * NN;
    int cnt = 0;
    for (int c = lane; c < NN; c += 32) {
        unsigned m = __ballot_sync(FULLM, ar[c] != 0.0f);
        cnt += __popc(m);
    }
    if (lane == 0) g_rowptr[row + 1] = cnt;
}

// ---------------- CSR build: single-block prefix scan ------------------------
__global__ void k_scan() {
    __shared__ int sm[1024];
    int t = threadIdx.x;
    int base = 1 + t * 4;
    int c[4]; int l = 0;
    for (int i = 0; i < 4; i++) { c[i] = g_rowptr[base + i]; l += c[i]; }
    sm[t] = l;
    __syncthreads();
    for (int off = 1; off < 1024; off <<= 1) {
        int v = (t >= off) ? sm[t - off] : 0;
        __syncthreads();
        sm[t] += v;
        __syncthreads();
    }
    int run = sm[t] - l;           // exclusive prefix of this thread's group
    for (int i = 0; i < 4; i++) { run += c[i]; g_rowptr[base + i] = run; }
}

// ---------------- CSR build: fill cols + L values ----------------------------
__global__ void k_fill(const float* __restrict__ A, const float* __restrict__ Lm) {
    int row  = blockIdx.x * 8 + (threadIdx.x >> 5);
    int lane = threadIdx.x & 31;
    if (row >= NN) return;
    const float* ar = A  + (size_t)row * NN;
    const float* lr = Lm + (size_t)row * NN;
    int base = g_rowptr[row];
    int off = 0;
    for (int c0 = 0; c0 < NN; c0 += 32) {
        int c = c0 + lane;
        float a = ar[c];
        unsigned m = __ballot_sync(FULLM, a != 0.0f);
        if (a != 0.0f) {
            int pos = base + off + __popc(m & ((1u << lane) - 1u));
            if (pos < NNZ_MAX) { g_cols[pos] = c; g_lvals[pos] = lr[c]; }
        }
        off += __popc(m);
    }
}

// ---------------- orth_loss --------------------------------------------------
__global__ void k_orth(const float* __restrict__ U, float* out) {
    const int pk[10] = {0,1,2,3, 0,0,0, 1,1, 2};
    const int pl[10] = {0,1,2,3, 1,2,3, 2,3, 3};
    int k = pk[blockIdx.x], l = pl[blockIdx.x];
    __shared__ float sred[256];
    const float* Ua = U + (size_t)k * DD * SS;
    const float* Ub = U + (size_t)l * DD * SS;
    float local = 0.f;
    for (int idx = threadIdx.x; idx < SS * SS; idx += 256) {
        int a = idx >> 5, b = idx & 31;
        float g = 0.f;
        for (int d = 0; d < DD; d++)
            g += Ua[d * SS + a] * Ub[d * SS + b];
        if (k == l && a == b) g -= 1.f;
        local += g * g;
    }
    sred[threadIdx.x] = local;
    __syncthreads();
    for (int o = 128; o > 0; o >>= 1) {
        if (threadIdx.x < o) sred[threadIdx.x] += sred[threadIdx.x + o];
        __syncthreads();
    }
    if (threadIdx.x == 0) atomicAdd(&out[NDOUT], sred[0]);
}

// ---------------- Z[k] = U[k]^T @ hops[k]^T  (stored as (k,n,s)) -------------
__global__ void k_Z(const float* __restrict__ hops, const float* __restrict__ U) {
    __shared__ __align__(16) float sU[64 * 32];   // d-chunk x s
    __shared__ float sh[32][65];                  // n x d-chunk (padded)
    int k    = blockIdx.y;
    int n0   = blockIdx.x * 32;
    int nloc = threadIdx.x >> 3;
    int sq   = threadIdx.x & 7;
    float a0 = 0.f, a1 = 0.f, a2 = 0.f, a3 = 0.f;
    for (int d0 = 0; d0 < DD; d0 += 64) {
        for (int i = threadIdx.x; i < 64 * 32; i += 256)
            sU[i] = U[(size_t)k * DD * SS + (size_t)(d0 + (i >> 5)) * SS + (i & 31)];
        for (int i = threadIdx.x; i < 32 * 64; i += 256) {
            int nn = i >> 6, dd = i & 63;
            sh[nn][dd] = hops[(size_t)k * NN * DD + (size_t)(n0 + nn) * DD + d0 + dd];
        }
        __syncthreads();
        #pragma unroll 8
        for (int dd = 0; dd < 64; dd++) {
            float h = sh[nloc][dd];
            float4 u = *(const float4*)&sU[dd * 32 + sq * 4];
            a0 += h * u.x; a1 += h * u.y; a2 += h * u.z; a3 += h * u.w;
        }
        __syncthreads();
    }
    float* zp = &g_Z[(size_t)k * NN * SS + (size_t)(n0 + nloc) * SS + sq * 4];
    zp[0] = a0; zp[1] = a1; zp[2] = a2; zp[3] = a3;
}

// ---------------- M partials: Z Z^T over n-chunks ----------------------------
__global__ void k_Mpart() {
    int k = blockIdx.y, c = blockIdx.x;
    int t = threadIdx.x;            // 64 threads
    int a = t >> 3, b = t & 7;      // 8x8 thread grid, 4x4 regs each
    float acc[4][4];
    for (int i = 0; i < 4; i++) for (int j = 0; j < 4; j++) acc[i][j] = 0.f;
    const float* Zb = g_Z + (size_t)k * NN * SS;
    for (int n = c * 256; n < c * 256 + 256; n++) {
        const float4* row = (const float4*)(Zb + (size_t)n * SS);
        float4 za = __ldg(&row[a]);
        float4 zb = __ldg(&row[b]);
        float xa[4] = {za.x, za.y, za.z, za.w};
        float xb[4] = {zb.x, zb.y, zb.z, zb.w};
        #pragma unroll
        for (int i = 0; i < 4; i++)
            #pragma unroll
            for (int j = 0; j < 4; j++)
                acc[i][j] += xa[i] * xb[j];
    }
    float* mp = g_Mp + ((size_t)(k * 16 + c)) * SS * SS;
    for (int i = 0; i < 4; i++)
        for (int j = 0; j < 4; j++)
            mp[(4 * a + i) * SS + 4 * b + j] = acc[i][j];
}

// ---------------- reduce partials: M = I + coeff * ZZ^T ----------------------
__global__ void k_Mred() {
    int k = blockIdx.x, t = threadIdx.x;   // 1024 threads
    float acc = 0.f;
    for (int c = 0; c < 16; c++)
        acc += g_Mp[((size_t)(k * 16 + c)) * 1024 + t];
    const float coeff = (float)SS / ((float)NN * 0.25f);  // S/(N*EPS^2)
    g_M[k * 1024 + t] = coeff * acc + (((t >> 5) == (t & 31)) ? 1.f : 0.f);
}

// ---------------- 32x32 SPD inverse via warp Gauss-Jordan --------------------
__global__ void k_inv() {
    int k = blockIdx.x, j = threadIdx.x;   // 32 threads
    __shared__ float a[32][64];
    for (int r = 0; r < 32; r++) {
        a[r][j]      = g_M[k * 1024 + r * 32 + j];
        a[r][32 + j] = (r == j) ? 1.f : 0.f;
    }
    __syncwarp();
    for (int p = 0; p < 32; p++) {
        float pv = 1.0f / a[p][p];
        __syncwarp();
        a[p][j]      *= pv;
        a[p][32 + j] *= pv;
        __syncwarp();
        for (int r = 0; r < 32; r++) {
            if (r == p) continue;
            float f = a[r][p];
            __syncwarp();
            a[r][j]      -= f * a[p][j];
            a[r][32 + j] -= f * a[p][32 + j];
            __syncwarp();
        }
        __syncwarp();
    }
    for (int r = 0; r < 32; r++)
        g_Minv[k * 1024 + r * 32 + j] = a[r][32 + j];
}

// ---------------- MZ = M_inv @ Z  (M_inv symmetric) --------------------------
__global__ void k_MZ() {
    __shared__ float sM[1024];
    int k = blockIdx.y;
    for (int i = threadIdx.x; i < 1024; i += 256) sM[i] = g_Minv[k * 1024 + i];
    __syncthreads();
    int w = threadIdx.x >> 5, s = threadIdx.x & 31;
    int n = blockIdx.x * 8 + w;
    float z = g_Z[(size_t)k * NN * SS + (size_t)n * SS + s];
    float acc = 0.f;
    #pragma unroll
    for (int t = 0; t < 32; t++)
        acc += sM[t * 32 + s] * __shfl_sync(FULLM, z, t);  // symmetric: M[s][t]==M[t][s]
    g_MZ[(size_t)k * NN * SS + (size_t)n * SS + s] = acc;
}

// -------- fused: scores on CSR support -> softmax -> V = MZ @ alpha^T --------
__global__ void k_score() {
    __shared__ float s_z[32];
    __shared__ float s_sc[SCMAX];
    __shared__ float s_mz[MZC * 32];
    __shared__ float s_wmax[8], s_wsum[8];
    __shared__ float s_wv[8][32];
    __shared__ float s_bmax;
    int row = blockIdx.x, k = blockIdx.y;
    int w = threadIdx.x >> 5, lane = threadIdx.x & 31;
    int beg = g_rowptr[row];
    int nnz = g_rowptr[row + 1] - beg;
    if (threadIdx.x < 32)
        s_z[lane] = g_Z[(size_t)k * NN * SS + (size_t)row * SS + lane];
    __syncthreads();
    float zl = s_z[lane];
    const float* MZb = g_MZ + (size_t)k * NN * SS;

    float wmax = -1e30f;
    for (int jj = w; jj < nnz; jj += 8) {
        int col = g_cols[beg + jj];
        float mzv = MZb[(size_t)col * SS + lane];
        if (jj < MZC) s_mz[jj * 32 + lane] = mzv;
        float p = zl * mzv;
        #pragma unroll
        for (int o = 16; o > 0; o >>= 1) p += __shfl_xor_sync(FULLM, p, o);
        if (jj < SCMAX && lane == 0) s_sc[jj] = p;
        wmax = fmaxf(wmax, p);
    }
    if (lane == 0) s_wmax[w] = wmax;
    __syncthreads();
    if (threadIdx.x == 0) {
        float m = s_wmax[0];
        for (int i = 1; i < 8; i++) m = fmaxf(m, s_wmax[i]);
        s_bmax = m;
    }
    __syncthreads();
    float bmax = s_bmax;

    float vsum = 0.f, esum = 0.f;
    for (int jj = w; jj < nnz; jj += 8) {
        float mzv;
        if (jj < MZC) mzv = s_mz[jj * 32 + lane];
        else {
            int col = g_cols[beg + jj];
            mzv = MZb[(size_t)col * SS + lane];
        }
        float sc;
        if (jj < SCMAX) sc = s_sc[jj];
        else {
            float p = zl * mzv;
            #pragma unroll
            for (int o = 16; o > 0; o >>= 1) p += __shfl_xor_sync(FULLM, p, o);
            sc = p;
        }
        float e = __expf(sc - bmax);
        esum += e;
        vsum += e * mzv;
    }
    s_wv[w][lane] = vsum;
    if (lane == 0) s_wsum[w] = esum;
    __syncthreads();
    if (w == 0) {
        float v = 0.f, es = 0.f;
        for (int i = 0; i < 8; i++) { v += s_wv[i][lane]; es += s_wsum[i]; }
        g_V[(size_t)k * NN * SS + (size_t)row * SS + lane] = v / es;
    }
}

// ---------------- H_agg = sum_k w_k * V_k @ U_k^T  (N x D) -------------------
__global__ void __launch_bounds__(256) k_vu(const float* __restrict__ U) {
    __shared__ __align__(16) float sV[32 * 32];
    int d = threadIdx.x, n0 = blockIdx.x * 32;
    float acc[32];
    #pragma unroll
    for (int i = 0; i < 32; i++) acc[i] = 0.f;
    for (int k = 0; k < KK; k++) {
        float wk = g_w[k];
        float u[32];
        const float4* up = (const float4*)(U + (size_t)k * DD * SS + (size_t)d * SS);
        #pragma unroll
        for (int i = 0; i < 8; i++) {
            float4 t = __ldg(&up[i]);
            u[4*i]   = wk * t.x; u[4*i+1] = wk * t.y;
            u[4*i+2] = wk * t.z; u[4*i+3] = wk * t.w;
        }
        __syncthreads();
        for (int i = threadIdx.x; i < 1024; i += 256)
            sV[i] = g_V[(size_t)k * NN * SS + (size_t)n0 * SS + i];
        __syncthreads();
        #pragma unroll 4
        for (int n = 0; n < 32; n++) {
            const float4* vp = (const float4*)&sV[n * 32];
            float a = 0.f;
            #pragma unroll
            for (int s4 = 0; s4 < 8; s4++) {
                float4 v = vp[s4];
                a += u[4*s4]*v.x + u[4*s4+1]*v.y + u[4*s4+2]*v.z + u[4*s4+3]*v.w;
            }
            acc[n] += a;
        }
    }
    for (int n = 0; n < 32; n++)
        g_Hagg[(size_t)(n0 + n) * DD + d] = acc[n];
}

// ------- H_half = hops0 + ETA*H_agg - ETA*lambda*(L@H_agg); soft threshold ----
__global__ void k_lap1(const float* __restrict__ hops, const float* __restrict__ lamp,
                       const float* __restrict__ thr, float* __restrict__ out) {
    int row = blockIdx.x, d = threadIdx.x;
    int beg = g_rowptr[row], end = g_rowptr[row + 1];
    float lam = lamp[0];
    float y = 0.f;
    for (int e = beg; e < end; e++) {
        int j = g_cols[e];
        float lv = g_lvals[e];
        y += lv * g_Hagg[(size_t)j * DD + d];
    }
    float hh = hops[(size_t)row * DD + d]
             + 0.5f * g_Hagg[(size_t)row * DD + d]
             - 0.5f * lam * y;
    float t = thr[d];
    float o = fmaxf(fabsf(hh) - t, 0.f);
    o = (hh < 0.f) ? -o : o;
    out[(size_t)row * DD + d] = o;
}

// ---------------- lap_smooth = sum(H_out * (L @ H_out)) ----------------------
__global__ void k_lap2(const float* __restrict__ H, float* out) {
    __shared__ float sred[256];
    int row = blockIdx.x, d = threadIdx.x;
    int beg = g_rowptr[row], end = g_rowptr[row + 1];
    float y = 0.f;
    for (int e = beg; e < end; e++) {
        int j = g_cols[e];
        float lv = g_lvals[e];
        y += lv * H[(size_t)j * DD + d];
    }
    sred[threadIdx.x] = H[(size_t)row * DD + d] * y;
    __syncthreads();
    for (int o = 128; o > 0; o >>= 1) {
        if (threadIdx.x < o) sred[threadIdx.x] += sred[threadIdx.x + o];
        __syncthreads();
    }
    if (threadIdx.x == 0) atomicAdd(&out[NDOUT + 1], sred[0]);
}

// -----------------------------------------------------------------------------
extern "C" void kernel_launch(void* const* d_in, const int* in_sizes, int n_in,
                              void* d_out, int out_size) {
    const float* hops = (const float*)d_in[0];  // (K,N,D)
    const float* A    = (const float*)d_in[1];  // (N,N)
    const float* Lm   = (const float*)d_in[2];  // (N,N)
    const float* U    = (const float*)d_in[3];  // (K,D,S)
    const float* hw   = (const float*)d_in[4];  // (K,)
    const float* thr  = (const float*)d_in[5];  // (D,)
    const float* lam  = (const float*)d_in[6];  // scalar
    float* out = (float*)d_out;

    k_init<<<1, 32>>>(hw, out, out_size);
    k_count<<<NN / 8, 256>>>(A);
    k_scan<<<1, 1024>>>();
    k_fill<<<NN / 8, 256>>>(A, Lm);
    k_orth<<<10, 256>>>(U, out);

    dim3 gz(NN / 32, KK);
    k_Z<<<gz, 256>>>(hops, U);
    dim3 gm(16, KK);
    k_Mpart<<<gm, 64>>>();
    k_Mred<<<KK, 1024>>>();
    k_inv<<<KK, 32>>>();
    dim3 gmz(NN / 8, KK);
    k_MZ<<<gmz, 256>>>();
    dim3 gs(NN, KK);
    k_score<<<gs, 256>>>();
    k_vu<<<NN / 32, 256>>>(U);
    k_lap1<<<NN, 256>>>(hops, lam, thr, out);
    k_lap2<<<NN, 256>>>(out, out);
}

// round 2
// speedup vs baseline: 1.3282x; 1.3282x over previous
#include <cuda_runtime.h>
#include <math.h>

#define NN 4096
#define DD 256
#define SS 32
#define KK 4
#define NDOUT (NN*DD)
#define NNZ_MAX (1<<20)
#define FULLM 0xffffffffu

// ---------------- scratch (device globals; no allocation allowed) -----------
__device__ int   g_rowbeg[NN];
__device__ int   g_rowcnt[NN];
__device__ int   g_nnz;
__device__ int   g_cols[NNZ_MAX];
__device__ float g_lvals[NNZ_MAX];
__device__ __align__(16) float g_Z  [KK*NN*SS];
__device__ __align__(16) float g_MZ [KK*NN*SS];
__device__ __align__(16) float g_V  [KK*NN*SS];
__device__ __align__(16) float g_W  [KK*NN*SS];
__device__ float g_M   [KK*SS*SS];
__device__ float g_Mp  [KK*16*SS*SS];
__device__ float g_Minv[KK*SS*SS];
__device__ float g_w[KK];

// ---------------- init: w = softmax(hop_weights), zero accumulators ---------
__global__ void k_init(const float* hw, float* out, int out_size) {
    if (threadIdx.x == 0) {
        float m = hw[0];
        for (int i = 1; i < KK; i++) m = fmaxf(m, hw[i]);
        float e[KK]; float s = 0.f;
        for (int i = 0; i < KK; i++) { e[i] = expf(hw[i] - m); s += e[i]; }
        for (int i = 0; i < KK; i++) {
            float w = e[i] / s;
            g_w[i] = w;
            if (NDOUT + 2 + i < out_size) out[NDOUT + 2 + i] = w;
        }
        if (NDOUT     < out_size) out[NDOUT]     = 0.f;
        if (NDOUT + 1 < out_size) out[NDOUT + 1] = 0.f;
        g_nnz = 0;
    }
}

// ------- single-pass CSR build: block per row, float4 scan, ordered append ---
__global__ void k_build(const float* __restrict__ A, const float* __restrict__ Lm) {
    __shared__ int ssc[256];
    __shared__ int slist[16 * 256];   // slot j of thread t at slist[j*256+t]
    __shared__ int s_base;
    int row = blockIdx.x, t = threadIdx.x;
    const float4* ar = (const float4*)(A + (size_t)row * NN);
    int c = 0;
    #pragma unroll
    for (int i = 0; i < 4; i++) {
        float4 f = ar[t * 4 + i];
        int cb = t * 16 + i * 4;
        if (f.x != 0.f) slist[(c++) * 256 + t] = cb;
        if (f.y != 0.f) slist[(c++) * 256 + t] = cb + 1;
        if (f.z != 0.f) slist[(c++) * 256 + t] = cb + 2;
        if (f.w != 0.f) slist[(c++) * 256 + t] = cb + 3;
    }
    ssc[t] = c;
    __syncthreads();
    for (int off = 1; off < 256; off <<= 1) {
        int v = (t >= off) ? ssc[t - off] : 0;
        __syncthreads();
        ssc[t] += v;
        __syncthreads();
    }
    int excl = ssc[t] - c;
    if (t == 0) {
        int total = ssc[255];
        s_base = atomicAdd(&g_nnz, total);
        g_rowcnt[row] = total;
    }
    __syncthreads();
    int base = s_base;
    if (t == 0) g_rowbeg[row] = base;
    const float* lr = Lm + (size_t)row * NN;
    for (int j = 0; j < c; j++) {
        int col = slist[j * 256 + t];
        int pos = base + excl + j;
        if (pos < NNZ_MAX) { g_cols[pos] = col; g_lvals[pos] = lr[col]; }
    }
}

// ---------------- orth_loss (smem-tiled) -------------------------------------
__global__ void k_orth(const float* __restrict__ U, float* out) {
    const int pk[10] = {0,1,2,3, 0,0,0, 1,1, 2};
    const int pl[10] = {0,1,2,3, 1,2,3, 2,3, 3};
    int k = pk[blockIdx.x], l = pl[blockIdx.x];
    __shared__ float sa[32][33];
    __shared__ float sb[32][33];
    __shared__ float sred[256];
    const float* Ua = U + (size_t)k * DD * SS;
    const float* Ub = U + (size_t)l * DD * SS;
    int t = threadIdx.x;
    int b = t & 31, a0 = (t >> 5) * 4;
    float acc[4] = {0.f, 0.f, 0.f, 0.f};
    for (int d0 = 0; d0 < DD; d0 += 32) {
        for (int i = t; i < 1024; i += 256) {
            sa[i >> 5][i & 31] = Ua[(size_t)(d0 + (i >> 5)) * SS + (i & 31)];
            sb[i >> 5][i & 31] = Ub[(size_t)(d0 + (i >> 5)) * SS + (i & 31)];
        }
        __syncthreads();
        #pragma unroll 8
        for (int dd = 0; dd < 32; dd++) {
            float vb = sb[dd][b];
            #pragma unroll
            for (int i = 0; i < 4; i++) acc[i] += sa[dd][a0 + i] * vb;
        }
        __syncthreads();
    }
    float local = 0.f;
    #pragma unroll
    for (int i = 0; i < 4; i++) {
        float g = acc[i];
        if (k == l && (a0 + i) == b) g -= 1.f;
        local += g * g;
    }
    sred[t] = local;
    __syncthreads();
    for (int o = 128; o > 0; o >>= 1) {
        if (t < o) sred[t] += sred[t + o];
        __syncthreads();
    }
    if (t == 0) atomicAdd(&out[NDOUT], sred[0]);
}

// ---------------- Z[k] = U[k]^T @ hops[k]^T  (stored (k,n,s)) ----------------
__global__ void k_Z(const float* __restrict__ hops, const float* __restrict__ U) {
    __shared__ __align__(16) float sU[64 * 32];
    __shared__ float sh[32][65];
    int k    = blockIdx.y;
    int n0   = blockIdx.x * 32;
    int nloc = threadIdx.x >> 3;
    int sq   = threadIdx.x & 7;
    float a0 = 0.f, a1 = 0.f, a2 = 0.f, a3 = 0.f;
    for (int d0 = 0; d0 < DD; d0 += 64) {
        for (int i = threadIdx.x; i < 64 * 32; i += 256)
            sU[i] = U[(size_t)k * DD * SS + (size_t)(d0 + (i >> 5)) * SS + (i & 31)];
        for (int i = threadIdx.x; i < 32 * 64; i += 256) {
            int nn = i >> 6, dd = i & 63;
            sh[nn][dd] = hops[(size_t)k * NN * DD + (size_t)(n0 + nn) * DD + d0 + dd];
        }
        __syncthreads();
        #pragma unroll 8
        for (int dd = 0; dd < 64; dd++) {
            float h = sh[nloc][dd];
            float4 u = *(const float4*)&sU[dd * 32 + sq * 4];
            a0 += h * u.x; a1 += h * u.y; a2 += h * u.z; a3 += h * u.w;
        }
        __syncthreads();
    }
    float* zp = &g_Z[(size_t)k * NN * SS + (size_t)(n0 + nloc) * SS + sq * 4];
    zp[0] = a0; zp[1] = a1; zp[2] = a2; zp[3] = a3;
}

// ---------------- M partials: Z Z^T over n-chunks ----------------------------
__global__ void k_Mpart() {
    int k = blockIdx.y, c = blockIdx.x;
    int t = threadIdx.x;
    int a = t >> 3, b = t & 7;
    float acc[4][4];
    for (int i = 0; i < 4; i++) for (int j = 0; j < 4; j++) acc[i][j] = 0.f;
    const float* Zb = g_Z + (size_t)k * NN * SS;
    for (int n = c * 256; n < c * 256 + 256; n++) {
        const float4* row = (const float4*)(Zb + (size_t)n * SS);
        float4 za = __ldg(&row[a]);
        float4 zb = __ldg(&row[b]);
        float xa[4] = {za.x, za.y, za.z, za.w};
        float xb[4] = {zb.x, zb.y, zb.z, zb.w};
        #pragma unroll
        for (int i = 0; i < 4; i++)
            #pragma unroll
            for (int j = 0; j < 4; j++)
                acc[i][j] += xa[i] * xb[j];
    }
    float* mp = g_Mp + ((size_t)(k * 16 + c)) * SS * SS;
    for (int i = 0; i < 4; i++)
        for (int j = 0; j < 4; j++)
            mp[(4 * a + i) * SS + 4 * b + j] = acc[i][j];
}

__global__ void k_Mred() {
    int k = blockIdx.x, t = threadIdx.x;
    float acc = 0.f;
    for (int c = 0; c < 16; c++)
        acc += g_Mp[((size_t)(k * 16 + c)) * 1024 + t];
    const float coeff = (float)SS / ((float)NN * 0.25f);
    g_M[k * 1024 + t] = coeff * acc + (((t >> 5) == (t & 31)) ? 1.f : 0.f);
}

// ---------------- 32x32 SPD inverse via warp Gauss-Jordan --------------------
__global__ void k_inv() {
    int k = blockIdx.x, j = threadIdx.x;
    __shared__ float a[32][64];
    for (int r = 0; r < 32; r++) {
        a[r][j]      = g_M[k * 1024 + r * 32 + j];
        a[r][32 + j] = (r == j) ? 1.f : 0.f;
    }
    __syncwarp();
    for (int p = 0; p < 32; p++) {
        float pv = 1.0f / a[p][p];
        __syncwarp();
        a[p][j]      *= pv;
        a[p][32 + j] *= pv;
        __syncwarp();
        for (int r = 0; r < 32; r++) {
            if (r == p) continue;
            float f = a[r][p];
            __syncwarp();
            a[r][j]      -= f * a[p][j];
            a[r][32 + j] -= f * a[p][32 + j];
            __syncwarp();
        }
        __syncwarp();
    }
    for (int r = 0; r < 32; r++)
        g_Minv[k * 1024 + r * 32 + j] = a[r][32 + j];
}

// ---------------- MZ = M_inv @ Z ---------------------------------------------
__global__ void k_MZ() {
    __shared__ float sM[1024];
    int k = blockIdx.y;
    for (int i = threadIdx.x; i < 1024; i += 256) sM[i] = g_Minv[k * 1024 + i];
    __syncthreads();
    int w = threadIdx.x >> 5, s = threadIdx.x & 31;
    int n = blockIdx.x * 8 + w;
    float z = g_Z[(size_t)k * NN * SS + (size_t)n * SS + s];
    float acc = 0.f;
    #pragma unroll
    for (int t = 0; t < 32; t++)
        acc += sM[t * 32 + s] * __shfl_sync(FULLM, z, t);
    g_MZ[(size_t)k * NN * SS + (size_t)n * SS + s] = acc;
}

// -------- fused: online softmax over CSR support -> V = MZ @ alpha^T ---------
__global__ void k_score() {
    __shared__ int   s_cols[512];
    __shared__ float s_z[32];
    __shared__ float s_m[8], s_l[8];
    __shared__ float s_v[8][32];
    int row = blockIdx.x, k = blockIdx.y;
    int w = threadIdx.x >> 5, lane = threadIdx.x & 31;
    int beg = g_rowbeg[row];
    int cnt = g_rowcnt[row];
    if (threadIdx.x < 32)
        s_z[lane] = g_Z[(size_t)k * NN * SS + (size_t)row * SS + lane];
    __syncthreads();
    float zl = s_z[lane];
    const float* MZb = g_MZ + (size_t)k * NN * SS;

    float m = -1e30f, l = 0.f, vac = 0.f;
    for (int c0 = 0; c0 < cnt; c0 += 512) {
        int mm = min(512, cnt - c0);
        __syncthreads();
        for (int i = threadIdx.x; i < mm; i += 256) s_cols[i] = g_cols[beg + c0 + i];
        __syncthreads();
        for (int jj = w; jj < mm; jj += 8) {
            int col = s_cols[jj];
            float mzv = MZb[(size_t)col * SS + lane];
            float p = zl * mzv;
            #pragma unroll
            for (int o = 16; o > 0; o >>= 1) p += __shfl_xor_sync(FULLM, p, o);
            float nm = fmaxf(m, p);
            float sc = __expf(m - nm);
            float e  = __expf(p - nm);
            l = l * sc + e;
            vac = vac * sc + e * mzv;
            m = nm;
        }
    }
    if (lane == 0) s_m[w] = m;
    __syncthreads();
    float gm = s_m[0];
    #pragma unroll
    for (int i = 1; i < 8; i++) gm = fmaxf(gm, s_m[i]);
    float scale = __expf(m - gm);
    if (lane == 0) s_l[w] = l * scale;
    s_v[w][lane] = vac * scale;
    __syncthreads();
    if (w == 0) {
        float vs = 0.f, ls = 0.f;
        #pragma unroll
        for (int i = 0; i < 8; i++) { vs += s_v[i][lane]; ls += s_l[i]; }
        g_V[(size_t)k * NN * SS + (size_t)row * SS + lane] = vs / ls;
    }
}

// -------- W_k = w_k * (V_k - lambda * (L @ V_k))   (sparse L on N x 32) ------
__global__ void k_lapV(const float* __restrict__ lamp) {
    int k = blockIdx.y;
    int w = threadIdx.x >> 5, lane = threadIdx.x & 31;
    int row = blockIdx.x * 8 + w;
    float lam = lamp[0];
    int beg = g_rowbeg[row];
    int cnt = g_rowcnt[row];
    const float* Vb = g_V + (size_t)k * NN * SS;
    float y = 0.f;
    int e = 0;
    for (; e + 4 <= cnt; e += 4) {
        int   c0 = __ldg(&g_cols[beg + e]),     c1 = __ldg(&g_cols[beg + e + 1]);
        int   c2 = __ldg(&g_cols[beg + e + 2]), c3 = __ldg(&g_cols[beg + e + 3]);
        float l0 = __ldg(&g_lvals[beg + e]),     l1 = __ldg(&g_lvals[beg + e + 1]);
        float l2 = __ldg(&g_lvals[beg + e + 2]), l3 = __ldg(&g_lvals[beg + e + 3]);
        float v0 = Vb[(size_t)c0 * SS + lane];
        float v1 = Vb[(size_t)c1 * SS + lane];
        float v2 = Vb[(size_t)c2 * SS + lane];
        float v3 = Vb[(size_t)c3 * SS + lane];
        y += l0 * v0 + l1 * v1 + l2 * v2 + l3 * v3;
    }
    for (; e < cnt; e++) {
        int   c = __ldg(&g_cols[beg + e]);
        float lv = __ldg(&g_lvals[beg + e]);
        y += lv * Vb[(size_t)c * SS + lane];
    }
    float v = Vb[(size_t)row * SS + lane];
    g_W[(size_t)k * NN * SS + (size_t)row * SS + lane] = g_w[k] * (v - lam * y);
}

// ----- H_out = softthresh(hops0 + 0.5 * sum_k W_k @ U_k^T, thr)  (N x D) -----
__global__ void __launch_bounds__(256) k_vu(const float* __restrict__ U,
                                            const float* __restrict__ hops,
                                            const float* __restrict__ thr,
                                            float* __restrict__ out) {
    __shared__ __align__(16) float sW[32 * 32];
    int d = threadIdx.x, n0 = blockIdx.x * 32;
    float acc[32];
    #pragma unroll
    for (int i = 0; i < 32; i++) acc[i] = 0.f;
    for (int k = 0; k < KK; k++) {
        float u[32];
        const float4* up = (const float4*)(U + (size_t)k * DD * SS + (size_t)d * SS);
        #pragma unroll
        for (int i = 0; i < 8; i++) {
            float4 t = __ldg(&up[i]);
            u[4*i]   = t.x; u[4*i+1] = t.y;
            u[4*i+2] = t.z; u[4*i+3] = t.w;
        }
        __syncthreads();
        for (int i = threadIdx.x; i < 1024; i += 256)
            sW[i] = g_W[(size_t)k * NN * SS + (size_t)n0 * SS + i];
        __syncthreads();
        #pragma unroll 4
        for (int n = 0; n < 32; n++) {
            const float4* vp = (const float4*)&sW[n * 32];
            float a = 0.f;
            #pragma unroll
            for (int s4 = 0; s4 < 8; s4++) {
                float4 v = vp[s4];
                a += u[4*s4]*v.x + u[4*s4+1]*v.y + u[4*s4+2]*v.z + u[4*s4+3]*v.w;
            }
            acc[n] += a;
        }
    }
    float t = thr[d];
    for (int n = 0; n < 32; n++) {
        float hh = hops[(size_t)(n0 + n) * DD + d] + 0.5f * acc[n];
        float o = fmaxf(fabsf(hh) - t, 0.f);
        o = (hh < 0.f) ? -o : o;
        out[(size_t)(n0 + n) * DD + d] = o;
    }
}

// ---------------- lap_smooth = sum(H_out * (L @ H_out)) ----------------------
__global__ void k_lap2(const float* __restrict__ H, float* out) {
    __shared__ int   sc[512];
    __shared__ float sl[512];
    __shared__ float sred[256];
    int row = blockIdx.x, d = threadIdx.x;
    int beg = g_rowbeg[row];
    int cnt = g_rowcnt[row];
    float y = 0.f;
    for (int c0 = 0; c0 < cnt; c0 += 512) {
        int mm = min(512, cnt - c0);
        __syncthreads();
        for (int i = threadIdx.x; i < mm; i += 256) {
            sc[i] = g_cols[beg + c0 + i];
            sl[i] = g_lvals[beg + c0 + i];
        }
        __syncthreads();
        int e = 0;
        for (; e + 4 <= mm; e += 4) {
            float h0 = H[(size_t)sc[e]     * DD + d];
            float h1 = H[(size_t)sc[e + 1] * DD + d];
            float h2 = H[(size_t)sc[e + 2] * DD + d];
            float h3 = H[(size_t)sc[e + 3] * DD + d];
            y += sl[e] * h0 + sl[e + 1] * h1 + sl[e + 2] * h2 + sl[e + 3] * h3;
        }
        for (; e < mm; e++)
            y += sl[e] * H[(size_t)sc[e] * DD + d];
    }
    sred[threadIdx.x] = H[(size_t)row * DD + d] * y;
    __syncthreads();
    for (int o = 128; o > 0; o >>= 1) {
        if (threadIdx.x < o) sred[threadIdx.x] += sred[threadIdx.x + o];
        __syncthreads();
    }
    if (threadIdx.x == 0) atomicAdd(&out[NDOUT + 1], sred[0]);
}

// -----------------------------------------------------------------------------
extern "C" void kernel_launch(void* const* d_in, const int* in_sizes, int n_in,
                              void* d_out, int out_size) {
    const float* hops = (const float*)d_in[0];  // (K,N,D)
    const float* A    = (const float*)d_in[1];  // (N,N)
    const float* Lm   = (const float*)d_in[2];  // (N,N)
    const float* U    = (const float*)d_in[3];  // (K,D,S)
    const float* hw   = (const float*)d_in[4];  // (K,)
    const float* thr  = (const float*)d_in[5];  // (D,)
    const float* lam  = (const float*)d_in[6];  // scalar
    float* out = (float*)d_out;

    k_init<<<1, 32>>>(hw, out, out_size);
    k_build<<<NN, 256>>>(A, Lm);
    k_orth<<<10, 256>>>(U, out);

    dim3 gz(NN / 32, KK);
    k_Z<<<gz, 256>>>(hops, U);
    dim3 gm(16, KK);
    k_Mpart<<<gm, 64>>>();
    k_Mred<<<KK, 1024>>>();
    k_inv<<<KK, 32>>>();
    dim3 gmz(NN / 8, KK);
    k_MZ<<<gmz, 256>>>();
    dim3 gs(NN, KK);
    k_score<<<gs, 256>>>();
    k_lapV<<<gmz, 256>>>(lam);
    k_vu<<<NN / 32, 256>>>(U, hops, thr, out);
    k_lap2<<<NN, 256>>>(out, out);
}